// round 15
// baseline (speedup 1.0000x reference)
#include <cuda_runtime.h>
#include <math_constants.h>
#include <cstdint>

// Problem shape (fixed by the dataset)
#define BB 4
#define HH 16
#define SS 2048
#define DD 64

#define BM 128   // query rows per CTA (8 warps x 16 rows)
#define BN 64    // key/value columns per tile
#define SA 68    // Q stride: mod 32 == 4 -> A-fragment loads conflict-free
#define SB 72    // K/V stride: mod 32 == 8 -> B-fragment loads conflict-free
#define NT (SS/BN)   // 32 tiles

// Dynamic smem layout (floats) — double-buffered K/V planes, no P buffer:
#define QS_OFF 0                        // [BM][SA] Q/8 fp32                 8704
#define K0_OFF (QS_OFF + BM*SA)         // [DD][SB] K tf32 buf0              4608
#define K1_OFF (K0_OFF + DD*SB)         // [DD][SB] K tf32 buf1              4608
#define V0_OFF (K1_OFF + DD*SB)         // [BN][SB] V tf32 buf0              4608
#define V1_OFF (V0_OFF + BN*SB)         // [BN][SB] V tf32 buf1              4608
#define SMEM_FLOATS (V1_OFF + BN*SB)    // 27136 floats = 108,544 B

__device__ __forceinline__ uint32_t tf32_rna(float x) {
    uint32_t u; asm("cvt.rna.tf32.f32 %0, %1;" : "=r"(u) : "f"(x)); return u;
}
__device__ __forceinline__ void split2(float x, float &h, float &l) {
    h = __uint_as_float(tf32_rna(x));
    l = __uint_as_float(tf32_rna(x - h));
}
__device__ __forceinline__ uint32_t fb(float x) { return __float_as_uint(x); }
__device__ __forceinline__ float4 cvt4(float4 v) {
    float4 r;
    r.x = __uint_as_float(tf32_rna(v.x));
    r.y = __uint_as_float(tf32_rna(v.y));
    r.z = __uint_as_float(tf32_rna(v.z));
    r.w = __uint_as_float(tf32_rna(v.w));
    return r;
}

__device__ __forceinline__ void mma8(float* c,
    uint32_t a0, uint32_t a1, uint32_t a2, uint32_t a3,
    uint32_t b0, uint32_t b1)
{
    asm volatile(
        "mma.sync.aligned.m16n8k8.row.col.f32.tf32.tf32.f32 "
        "{%0,%1,%2,%3},{%4,%5,%6,%7},{%8,%9},{%0,%1,%2,%3};"
        : "+f"(c[0]), "+f"(c[1]), "+f"(c[2]), "+f"(c[3])
        : "r"(a0), "r"(a1), "r"(a2), "r"(a3), "r"(b0), "r"(b1));
}

__global__ __launch_bounds__(256, 2)
void attn_mma_kernel(const float* __restrict__ q,
                     const float* __restrict__ k,
                     const float* __restrict__ v,
                     const int*   __restrict__ mask,
                     float* __restrict__ out_o,   // may be null
                     float* __restrict__ out_s)   // may be null
{
    extern __shared__ float sm[];
    float* qs = sm + QS_OFF;

    const int tid  = threadIdx.x;
    const int lane = tid & 31;
    const int w    = tid >> 5;       // warp 0..7 -> rows 16w..16w+15
    const int g    = lane >> 2;      // group 0..7
    const int t    = lane & 3;       // thread-in-group 0..3

    const int rb = blockIdx.x;
    const int h  = blockIdx.y;
    const int b  = blockIdx.z;

    const size_t bh = (size_t)b * HH + h;
    const float* qp = q + (bh * SS + (size_t)rb * BM) * DD;   // [BM][DD]
    const float* kp = k + bh * (size_t)DD * SS;               // [DD][SS]
    const float* vp = v + bh * (size_t)SS * DD;               // [SS][DD]
    const int*   mp = mask + ((size_t)b * SS + (size_t)rb * BM) * SS;  // [BM][SS]
    float* osp = out_s ? (out_s + (bh * SS + (size_t)rb * BM) * SS) : (float*)0;

    // Per-thread K/V-tile load coordinates (shared by prologue + pipeline)
    const int lr0 = tid >> 4;              // rows for it=0 chunk   (0..15)
    const int lc0 = (tid & 15) * 4;        // col*4
    // it-chunk r offset = it*16

    // ---- Load Q tile scaled by 1/8 (exact pow2), once ----
    #pragma unroll
    for (int it = 0; it < 8; ++it) {
        int id4 = tid + it * 256;
        int r  = id4 >> 4;
        int d4 = (id4 & 15) * 4;
        float4 qv = *(const float4*)(qp + (size_t)r * DD + d4);
        qv.x *= 0.125f; qv.y *= 0.125f; qv.z *= 0.125f; qv.w *= 0.125f;
        *(float4*)(qs + r * SA + d4) = qv;
    }

    // ---- Prologue: load K(0), V(0) into buffer 0 ----
    {
        #pragma unroll
        for (int it = 0; it < 4; ++it) {
            int r = lr0 + it * 16;
            *(float4*)(sm + K0_OFF + r * SB + lc0) =
                cvt4(*(const float4*)(kp + (size_t)r * SS + lc0));
            *(float4*)(sm + V0_OFF + r * SB + lc0) =
                cvt4(*(const float4*)(vp + (size_t)r * DD + lc0));
        }
    }

    const int row_l0 = 16 * w + g;
    const int row_l1 = row_l0 + 8;
    const int* mrow0 = mp + (size_t)row_l0 * SS;
    const int* mrow1 = mp + (size_t)row_l1 * SS;

    float oacc[8][4];
    float m0 = -CUDART_INF_F, m1 = -CUDART_INF_F, l0 = 0.f, l1 = 0.f;
    #pragma unroll
    for (int j = 0; j < 8; ++j)
        oacc[j][0] = oacc[j][1] = oacc[j][2] = oacc[j][3] = 0.f;

    #pragma unroll 1
    for (int jt = 0; jt < NT; ++jt) {
        const int s0 = jt * BN;
        const int s1 = s0 + BN;                 // next tile
        const bool pf = (jt + 1 < NT);
        const float* kcur = sm + ((jt & 1) ? K1_OFF : K0_OFF);
        const float* vcur = sm + ((jt & 1) ? V1_OFF : V0_OFF);
        float* knxt = sm + ((jt & 1) ? K0_OFF : K1_OFF);
        float* vnxt = sm + ((jt & 1) ? V0_OFF : V1_OFF);

        __syncthreads();   // all STS into cur (prev epoch) complete

        // Prefetch this tile's mask rows
        if (t == 0) {
            asm volatile("prefetch.global.L1 [%0];" :: "l"(mrow0 + s0));
            asm volatile("prefetch.global.L1 [%0];" :: "l"(mrow0 + s0 + 32));
            asm volatile("prefetch.global.L1 [%0];" :: "l"(mrow1 + s0));
            asm volatile("prefetch.global.L1 [%0];" :: "l"(mrow1 + s0 + 32));
        }

        // ---- issue LDG K(j+1) chunk A (rows lr0, lr0+16) ----
        float4 pfa, pfb;
        if (pf) {
            pfa = *(const float4*)(kp + (size_t)lr0 * SS + s1 + lc0);
            pfb = *(const float4*)(kp + (size_t)(lr0 + 16) * SS + s1 + lc0);
        }

        // ---- S = (Q/8) K : first half (k0 = 0..24), split-A 2xTF32 ----
        float sacc[8][4];
        #pragma unroll
        for (int j = 0; j < 8; ++j)
            sacc[j][0] = sacc[j][1] = sacc[j][2] = sacc[j][3] = 0.f;

        const float* q0 = qs + row_l0 * SA;
        const float* q1 = qs + row_l1 * SA;

        #pragma unroll 1
        for (int k0 = 0; k0 < 32; k0 += 8) {
            float a0h, a0l, a1h, a1l, a2h, a2l, a3h, a3l;
            split2(q0[k0 + t],     a0h, a0l);
            split2(q1[k0 + t],     a1h, a1l);
            split2(q0[k0 + t + 4], a2h, a2l);
            split2(q1[k0 + t + 4], a3h, a3l);
            const float* kbh  = kcur + (k0 + t) * SB + g;
            const float* kbh4 = kcur + (k0 + t + 4) * SB + g;
            #pragma unroll
            for (int j = 0; j < 8; ++j) {
                uint32_t b0h = fb(kbh[8 * j]), b1h = fb(kbh4[8 * j]);
                mma8(sacc[j], fb(a0h), fb(a1h), fb(a2h), fb(a3h), b0h, b1h);
                mma8(sacc[j], fb(a0l), fb(a1l), fb(a2l), fb(a3l), b0h, b1h);
            }
        }

        // ---- commit K chunk A; issue LDG K chunk B (rows +32, +48) ----
        if (pf) {
            *(float4*)(knxt + lr0 * SB + lc0)        = cvt4(pfa);
            *(float4*)(knxt + (lr0 + 16) * SB + lc0) = cvt4(pfb);
            pfa = *(const float4*)(kp + (size_t)(lr0 + 32) * SS + s1 + lc0);
            pfb = *(const float4*)(kp + (size_t)(lr0 + 48) * SS + s1 + lc0);
        }

        // ---- S second half (k0 = 32..56) ----
        #pragma unroll 1
        for (int k0 = 32; k0 < 64; k0 += 8) {
            float a0h, a0l, a1h, a1l, a2h, a2l, a3h, a3l;
            split2(q0[k0 + t],     a0h, a0l);
            split2(q1[k0 + t],     a1h, a1l);
            split2(q0[k0 + t + 4], a2h, a2l);
            split2(q1[k0 + t + 4], a3h, a3l);
            const float* kbh  = kcur + (k0 + t) * SB + g;
            const float* kbh4 = kcur + (k0 + t + 4) * SB + g;
            #pragma unroll
            for (int j = 0; j < 8; ++j) {
                uint32_t b0h = fb(kbh[8 * j]), b1h = fb(kbh4[8 * j]);
                mma8(sacc[j], fb(a0h), fb(a1h), fb(a2h), fb(a3h), b0h, b1h);
                mma8(sacc[j], fb(a0l), fb(a1l), fb(a2l), fb(a3l), b0h, b1h);
            }
        }

        // ---- commit K chunk B; issue LDG V(j+1) chunk A (rows 0..31) ----
        if (pf) {
            *(float4*)(knxt + (lr0 + 32) * SB + lc0) = cvt4(pfa);
            *(float4*)(knxt + (lr0 + 48) * SB + lc0) = cvt4(pfb);
            pfa = *(const float4*)(vp + (size_t)(s1 + lr0) * DD + lc0);
            pfb = *(const float4*)(vp + (size_t)(s1 + lr0 + 16) * DD + lc0);
        }

        // ---- Mask, store scores (streaming), online softmax ----
        float rmax0 = -CUDART_INF_F, rmax1 = -CUDART_INF_F;
        #pragma unroll
        for (int j = 0; j < 8; ++j) {
            const int coff = s0 + 2 * t + 8 * j;
            int2 mr0 = *(const int2*)(mrow0 + coff);
            int2 mr1 = *(const int2*)(mrow1 + coff);
            float s00 = (mr0.x == 0) ? -1e10f : sacc[j][0];
            float s01 = (mr0.y == 0) ? -1e10f : sacc[j][1];
            float s10 = (mr1.x == 0) ? -1e10f : sacc[j][2];
            float s11 = (mr1.y == 0) ? -1e10f : sacc[j][3];
            if (osp) {
                __stcs((float2*)(osp + (size_t)row_l0 * SS + coff), make_float2(s00, s01));
                __stcs((float2*)(osp + (size_t)row_l1 * SS + coff), make_float2(s10, s11));
            }
            sacc[j][0] = s00; sacc[j][1] = s01; sacc[j][2] = s10; sacc[j][3] = s11;
            rmax0 = fmaxf(rmax0, fmaxf(s00, s01));
            rmax1 = fmaxf(rmax1, fmaxf(s10, s11));
        }
        rmax0 = fmaxf(rmax0, __shfl_xor_sync(0xffffffffu, rmax0, 1));
        rmax0 = fmaxf(rmax0, __shfl_xor_sync(0xffffffffu, rmax0, 2));
        rmax1 = fmaxf(rmax1, __shfl_xor_sync(0xffffffffu, rmax1, 1));
        rmax1 = fmaxf(rmax1, __shfl_xor_sync(0xffffffffu, rmax1, 2));

        float mn0 = fmaxf(m0, rmax0), mn1 = fmaxf(m1, rmax1);
        float corr0 = __expf(m0 - mn0), corr1 = __expf(m1 - mn1);
        m0 = mn0; m1 = mn1;

        // P rounded to tf32 once, kept in sacc registers (no smem roundtrip);
        // rounded values feed BOTH PV numerator and l denominator.
        float rs0 = 0.f, rs1 = 0.f;
        #pragma unroll
        for (int j = 0; j < 8; ++j) {
            float p00 = __uint_as_float(tf32_rna(__expf(sacc[j][0] - mn0)));
            float p01 = __uint_as_float(tf32_rna(__expf(sacc[j][1] - mn0)));
            float p10 = __uint_as_float(tf32_rna(__expf(sacc[j][2] - mn1)));
            float p11 = __uint_as_float(tf32_rna(__expf(sacc[j][3] - mn1)));
            rs0 += p00 + p01; rs1 += p10 + p11;
            sacc[j][0] = p00; sacc[j][1] = p01;
            sacc[j][2] = p10; sacc[j][3] = p11;
        }
        rs0 += __shfl_xor_sync(0xffffffffu, rs0, 1);
        rs0 += __shfl_xor_sync(0xffffffffu, rs0, 2);
        rs1 += __shfl_xor_sync(0xffffffffu, rs1, 1);
        rs1 += __shfl_xor_sync(0xffffffffu, rs1, 2);
        l0 = l0 * corr0 + rs0;
        l1 = l1 * corr1 + rs1;
        #pragma unroll
        for (int j = 0; j < 8; ++j) {
            oacc[j][0] *= corr0; oacc[j][1] *= corr0;
            oacc[j][2] *= corr1; oacc[j][3] *= corr1;
        }

        // ---- commit V chunk A; issue LDG V chunk B (rows 32..63) ----
        if (pf) {
            *(float4*)(vnxt + lr0 * SB + lc0)        = cvt4(pfa);
            *(float4*)(vnxt + (lr0 + 16) * SB + lc0) = cvt4(pfb);
            pfa = *(const float4*)(vp + (size_t)(s1 + lr0 + 32) * DD + lc0);
            pfb = *(const float4*)(vp + (size_t)(s1 + lr0 + 48) * DD + lc0);
        }

        // ---- O += P V : A-fragments gathered from sacc via quad shuffles ----
        #pragma unroll 1
        for (int k0 = 0; k0 < BN; k0 += 8) {
            const int j = k0 >> 3;
            const int srcA = (lane & ~3) | (t >> 1);
            const int srcB = srcA + 2;
            float x0 = __shfl_sync(0xffffffffu, sacc[j][0], srcA);
            float x1 = __shfl_sync(0xffffffffu, sacc[j][1], srcA);
            float x2 = __shfl_sync(0xffffffffu, sacc[j][2], srcA);
            float x3 = __shfl_sync(0xffffffffu, sacc[j][3], srcA);
            float y0 = __shfl_sync(0xffffffffu, sacc[j][0], srcB);
            float y1 = __shfl_sync(0xffffffffu, sacc[j][1], srcB);
            float y2 = __shfl_sync(0xffffffffu, sacc[j][2], srcB);
            float y3 = __shfl_sync(0xffffffffu, sacc[j][3], srcB);
            const bool e = (t & 1);
            uint32_t a0 = fb(e ? x1 : x0);
            uint32_t a1 = fb(e ? x3 : x2);
            uint32_t a2 = fb(e ? y1 : y0);
            uint32_t a3 = fb(e ? y3 : y2);
            const float* vbh  = vcur + (k0 + t) * SB + g;
            const float* vbh4 = vcur + (k0 + t + 4) * SB + g;
            #pragma unroll
            for (int jj = 0; jj < 8; ++jj) {
                uint32_t b0h = fb(vbh[8 * jj]), b1h = fb(vbh4[8 * jj]);
                mma8(oacc[jj], a0, a1, a2, a3, b0h, b1h);
            }
        }

        // ---- commit V chunk B ----
        if (pf) {
            *(float4*)(vnxt + (lr0 + 32) * SB + lc0) = cvt4(pfa);
            *(float4*)(vnxt + (lr0 + 48) * SB + lc0) = cvt4(pfb);
        }
    }

    // ---- Normalize and write O ----
    if (out_o) {
        float inv0 = 1.0f / l0, inv1 = 1.0f / l1;
        float* op = out_o + (bh * SS + (size_t)rb * BM) * DD;
        #pragma unroll
        for (int j = 0; j < 8; ++j) {
            int dc = 8 * j + 2 * t;
            *(float2*)(op + (size_t)row_l0 * DD + dc) =
                make_float2(oacc[j][0] * inv0, oacc[j][1] * inv0);
            *(float2*)(op + (size_t)row_l1 * DD + dc) =
                make_float2(oacc[j][2] * inv1, oacc[j][3] * inv1);
        }
    }
}

extern "C" void kernel_launch(void* const* d_in, const int* in_sizes, int n_in,
                              void* d_out, int out_size)
{
    const float* q    = (const float*)d_in[0];
    const float* k    = (const float*)d_in[1];
    const float* v    = (const float*)d_in[2];
    const int*   mask = (const int*)  d_in[3];

    const long long OUT_O_N = (long long)BB * HH * SS * DD;   // 8388608
    const long long OUT_S_N = (long long)BB * HH * SS * SS;   // 268435456

    float* o_ptr = 0;
    float* s_ptr = 0;
    if ((long long)out_size == OUT_O_N + OUT_S_N) {
        o_ptr = (float*)d_out;
        s_ptr = (float*)d_out + OUT_O_N;
    } else if ((long long)out_size == OUT_O_N) {
        o_ptr = (float*)d_out;
    } else if ((long long)out_size == OUT_S_N) {
        s_ptr = (float*)d_out;
    } else {
        o_ptr = (float*)d_out;   // fallback: at least produce the primary output
    }

    const int smem_bytes = SMEM_FLOATS * (int)sizeof(float);  // 108,544 B
    cudaFuncSetAttribute(attn_mma_kernel,
                         cudaFuncAttributeMaxDynamicSharedMemorySize, smem_bytes);

    dim3 grid(SS / BM, HH, BB);   // (16, 16, 4) = 1024 CTAs
    dim3 block(256);
    attn_mma_kernel<<<grid, block, smem_bytes>>>(q, k, v, mask, o_ptr, s_ptr);
}

// round 16
// speedup vs baseline: 1.1460x; 1.1460x over previous
#include <cuda_runtime.h>
#include <math_constants.h>
#include <cstdint>

// Problem shape (fixed by the dataset)
#define BB 4
#define HH 16
#define SS 2048
#define DD 64

#define BM 128   // query rows per CTA (8 warps x 16 rows)
#define BN 64    // key/value columns per tile
#define SA 68    // stride for A-operand tiles (Q,P): mod 32 == 4 -> conflict-free
#define SB 72    // stride for B-operand tiles (K,V): mod 32 == 8 -> conflict-free

// Dynamic smem layout (floats):
#define QS_OFF 0                        // [BM][SA] Q/8 tf32 (row r, col d)   8704
#define KH_OFF (QS_OFF + BM*SA)         // [DD][SB] K tf32 (row d, col s)     4608
#define VH_OFF (KH_OFF + DD*SB)         // [BN][SB] V tf32 (row s, col d)     4608
#define PS_OFF (VH_OFF + BN*SB)         // [BM][SA] P tf32 (row r, col s)     8704
#define SMEM_FLOATS (PS_OFF + BM*SA)    // 26624 floats = 106,496 B

__device__ __forceinline__ uint32_t tf32_rna(float x) {
    uint32_t u; asm("cvt.rna.tf32.f32 %0, %1;" : "=r"(u) : "f"(x)); return u;
}
__device__ __forceinline__ uint32_t fb(float x) { return __float_as_uint(x); }

__device__ __forceinline__ void mma8(float* c,
    uint32_t a0, uint32_t a1, uint32_t a2, uint32_t a3,
    uint32_t b0, uint32_t b1)
{
    asm volatile(
        "mma.sync.aligned.m16n8k8.row.col.f32.tf32.tf32.f32 "
        "{%0,%1,%2,%3},{%4,%5,%6,%7},{%8,%9},{%0,%1,%2,%3};"
        : "+f"(c[0]), "+f"(c[1]), "+f"(c[2]), "+f"(c[3])
        : "r"(a0), "r"(a1), "r"(a2), "r"(a3), "r"(b0), "r"(b1));
}

__global__ __launch_bounds__(256, 2)
void attn_mma_kernel(const float* __restrict__ q,
                     const float* __restrict__ k,
                     const float* __restrict__ v,
                     const int*   __restrict__ mask,
                     float* __restrict__ out_o,   // may be null
                     float* __restrict__ out_s)   // may be null
{
    extern __shared__ float sm[];
    float* qs = sm + QS_OFF;
    float* kh = sm + KH_OFF;
    float* vh = sm + VH_OFF;
    float* ps = sm + PS_OFF;

    const int tid  = threadIdx.x;
    const int lane = tid & 31;
    const int w    = tid >> 5;       // warp 0..7 -> rows 16w..16w+15
    const int g    = lane >> 2;      // group 0..7
    const int t    = lane & 3;       // thread-in-group 0..3

    const int rb = blockIdx.x;
    const int h  = blockIdx.y;
    const int b  = blockIdx.z;

    const size_t bh = (size_t)b * HH + h;
    const float* qp = q + (bh * SS + (size_t)rb * BM) * DD;   // [BM][DD]
    const float* kp = k + bh * (size_t)DD * SS;               // [DD][SS]
    const float* vp = v + bh * (size_t)SS * DD;               // [SS][DD]
    const int*   mp = mask + ((size_t)b * SS + (size_t)rb * BM) * SS;  // [BM][SS]
    float* osp = out_s ? (out_s + (bh * SS + (size_t)rb * BM) * SS) : (float*)0;

    // ---- Load Q tile scaled by 1/8 (exact pow2), rounded to tf32, once ----
    #pragma unroll
    for (int it = 0; it < 8; ++it) {
        int id4 = tid + it * 256;
        int r  = id4 >> 4;
        int d4 = (id4 & 15) * 4;
        float4 qv = *(const float4*)(qp + (size_t)r * DD + d4);
        float4 hv;
        hv.x = __uint_as_float(tf32_rna(qv.x * 0.125f));
        hv.y = __uint_as_float(tf32_rna(qv.y * 0.125f));
        hv.z = __uint_as_float(tf32_rna(qv.z * 0.125f));
        hv.w = __uint_as_float(tf32_rna(qv.w * 0.125f));
        *(float4*)(qs + r * SA + d4) = hv;
    }

    const int row_l0 = 16 * w + g;
    const int row_l1 = row_l0 + 8;
    const int* mrow0 = mp + (size_t)row_l0 * SS;
    const int* mrow1 = mp + (size_t)row_l1 * SS;

    float oacc[8][4];
    float m0 = -CUDART_INF_F, m1 = -CUDART_INF_F, l0 = 0.f, l1 = 0.f;
    #pragma unroll
    for (int j = 0; j < 8; ++j)
        oacc[j][0] = oacc[j][1] = oacc[j][2] = oacc[j][3] = 0.f;

    for (int jt = 0; jt < SS / BN; ++jt) {
        const int s0 = jt * BN;

        // Prefetch this tile's mask rows (two 128B lines cover the BN=64 row)
        if (t == 0) {
            asm volatile("prefetch.global.L1 [%0];" :: "l"(mrow0 + s0));
            asm volatile("prefetch.global.L1 [%0];" :: "l"(mrow0 + s0 + 32));
            asm volatile("prefetch.global.L1 [%0];" :: "l"(mrow1 + s0));
            asm volatile("prefetch.global.L1 [%0];" :: "l"(mrow1 + s0 + 32));
        }

        __syncthreads();   // previous tile's consumers done before overwrite
        // ---- Load K tile [64 d][64 s], tf32 plane ----
        #pragma unroll
        for (int it = 0; it < 4; ++it) {
            int id4 = tid + it * 256;
            int r  = id4 >> 4;             // 0..63 (d)
            int c4 = (id4 & 15) * 4;       // 0..60 (s)
            float4 kv = *(const float4*)(kp + (size_t)r * SS + s0 + c4);
            float4 hv;
            hv.x = __uint_as_float(tf32_rna(kv.x));
            hv.y = __uint_as_float(tf32_rna(kv.y));
            hv.z = __uint_as_float(tf32_rna(kv.z));
            hv.w = __uint_as_float(tf32_rna(kv.w));
            *(float4*)(kh + r * SB + c4) = hv;
        }
        // ---- Load V tile [64 s][64 d], tf32 plane ----
        #pragma unroll
        for (int it = 0; it < 4; ++it) {
            int id4 = tid + it * 256;
            int r  = id4 >> 4;             // 0..63 (s)
            int c4 = (id4 & 15) * 4;       // 0..60 (d)
            float4 vv = *(const float4*)(vp + (size_t)(s0 + r) * DD + c4);
            float4 hv;
            hv.x = __uint_as_float(tf32_rna(vv.x));
            hv.y = __uint_as_float(tf32_rna(vv.y));
            hv.z = __uint_as_float(tf32_rna(vv.z));
            hv.w = __uint_as_float(tf32_rna(vv.w));
            *(float4*)(vh + r * SB + c4) = hv;
        }
        __syncthreads();

        // ---- S = (Q/8) K : 16x64 per warp, single-pass tf32 ----
        float sacc[8][4];
        #pragma unroll
        for (int j = 0; j < 8; ++j)
            sacc[j][0] = sacc[j][1] = sacc[j][2] = sacc[j][3] = 0.f;

        {
            const float* q0 = qs + row_l0 * SA;
            const float* q1 = qs + row_l1 * SA;
            #pragma unroll 1
            for (int k0 = 0; k0 < DD; k0 += 8) {
                uint32_t a0 = fb(q0[k0 + t]);
                uint32_t a1 = fb(q1[k0 + t]);
                uint32_t a2 = fb(q0[k0 + t + 4]);
                uint32_t a3 = fb(q1[k0 + t + 4]);
                const float* kbh  = kh + (k0 + t) * SB + g;
                const float* kbh4 = kh + (k0 + t + 4) * SB + g;
                #pragma unroll
                for (int j = 0; j < 8; ++j) {
                    uint32_t b0h = fb(kbh[8 * j]), b1h = fb(kbh4[8 * j]);
                    mma8(sacc[j], a0, a1, a2, a3, b0h, b1h);
                }
            }
        }

        // ---- Mask, store scores (streaming), online softmax ----
        float rmax0 = -CUDART_INF_F, rmax1 = -CUDART_INF_F;
        #pragma unroll
        for (int j = 0; j < 8; ++j) {
            const int coff = s0 + 2 * t + 8 * j;
            int2 mr0 = *(const int2*)(mrow0 + coff);
            int2 mr1 = *(const int2*)(mrow1 + coff);
            float s00 = (mr0.x == 0) ? -1e10f : sacc[j][0];
            float s01 = (mr0.y == 0) ? -1e10f : sacc[j][1];
            float s10 = (mr1.x == 0) ? -1e10f : sacc[j][2];
            float s11 = (mr1.y == 0) ? -1e10f : sacc[j][3];
            if (osp) {
                __stcs((float2*)(osp + (size_t)row_l0 * SS + coff), make_float2(s00, s01));
                __stcs((float2*)(osp + (size_t)row_l1 * SS + coff), make_float2(s10, s11));
            }
            sacc[j][0] = s00; sacc[j][1] = s01; sacc[j][2] = s10; sacc[j][3] = s11;
            rmax0 = fmaxf(rmax0, fmaxf(s00, s01));
            rmax1 = fmaxf(rmax1, fmaxf(s10, s11));
        }
        rmax0 = fmaxf(rmax0, __shfl_xor_sync(0xffffffffu, rmax0, 1));
        rmax0 = fmaxf(rmax0, __shfl_xor_sync(0xffffffffu, rmax0, 2));
        rmax1 = fmaxf(rmax1, __shfl_xor_sync(0xffffffffu, rmax1, 1));
        rmax1 = fmaxf(rmax1, __shfl_xor_sync(0xffffffffu, rmax1, 2));

        float mn0 = fmaxf(m0, rmax0), mn1 = fmaxf(m1, rmax1);
        float corr0 = __expf(m0 - mn0), corr1 = __expf(m1 - mn1);
        m0 = mn0; m1 = mn1;

        // P rounded to tf32 once; rounded values used for BOTH numerator (PV)
        // and denominator (l) so normalization errors partially cancel.
        float rs0 = 0.f, rs1 = 0.f;
        float* p0 = ps + row_l0 * SA + 2 * t;
        float* p1 = ps + row_l1 * SA + 2 * t;
        #pragma unroll
        for (int j = 0; j < 8; ++j) {
            float p00 = __uint_as_float(tf32_rna(__expf(sacc[j][0] - mn0)));
            float p01 = __uint_as_float(tf32_rna(__expf(sacc[j][1] - mn0)));
            float p10 = __uint_as_float(tf32_rna(__expf(sacc[j][2] - mn1)));
            float p11 = __uint_as_float(tf32_rna(__expf(sacc[j][3] - mn1)));
            rs0 += p00 + p01; rs1 += p10 + p11;
            *(float2*)(p0 + 8 * j) = make_float2(p00, p01);
            *(float2*)(p1 + 8 * j) = make_float2(p10, p11);
        }
        rs0 += __shfl_xor_sync(0xffffffffu, rs0, 1);
        rs0 += __shfl_xor_sync(0xffffffffu, rs0, 2);
        rs1 += __shfl_xor_sync(0xffffffffu, rs1, 1);
        rs1 += __shfl_xor_sync(0xffffffffu, rs1, 2);
        l0 = l0 * corr0 + rs0;
        l1 = l1 * corr1 + rs1;
        #pragma unroll
        for (int j = 0; j < 8; ++j) {
            oacc[j][0] *= corr0; oacc[j][1] *= corr0;
            oacc[j][2] *= corr1; oacc[j][3] *= corr1;
        }
        __syncwarp();   // ps rows warp-private: order STS -> LDS within warp

        // ---- O += P V : 16x64 per warp, single-pass tf32 (P already tf32) ----
        {
            const float* pr0 = ps + row_l0 * SA;
            const float* pr1 = ps + row_l1 * SA;
            #pragma unroll 1
            for (int k0 = 0; k0 < BN; k0 += 8) {
                uint32_t a0 = fb(pr0[k0 + t]);
                uint32_t a1 = fb(pr1[k0 + t]);
                uint32_t a2 = fb(pr0[k0 + t + 4]);
                uint32_t a3 = fb(pr1[k0 + t + 4]);
                const float* vbh  = vh + (k0 + t) * SB + g;
                const float* vbh4 = vh + (k0 + t + 4) * SB + g;
                #pragma unroll
                for (int j = 0; j < 8; ++j) {
                    uint32_t b0h = fb(vbh[8 * j]), b1h = fb(vbh4[8 * j]);
                    mma8(oacc[j], a0, a1, a2, a3, b0h, b1h);
                }
            }
        }
    }

    // ---- Normalize and write O ----
    if (out_o) {
        float inv0 = 1.0f / l0, inv1 = 1.0f / l1;
        float* op = out_o + (bh * SS + (size_t)rb * BM) * DD;
        #pragma unroll
        for (int j = 0; j < 8; ++j) {
            int dc = 8 * j + 2 * t;
            *(float2*)(op + (size_t)row_l0 * DD + dc) =
                make_float2(oacc[j][0] * inv0, oacc[j][1] * inv0);
            *(float2*)(op + (size_t)row_l1 * DD + dc) =
                make_float2(oacc[j][2] * inv1, oacc[j][3] * inv1);
        }
    }
}

extern "C" void kernel_launch(void* const* d_in, const int* in_sizes, int n_in,
                              void* d_out, int out_size)
{
    const float* q    = (const float*)d_in[0];
    const float* k    = (const float*)d_in[1];
    const float* v    = (const float*)d_in[2];
    const int*   mask = (const int*)  d_in[3];

    const long long OUT_O_N = (long long)BB * HH * SS * DD;   // 8388608
    const long long OUT_S_N = (long long)BB * HH * SS * SS;   // 268435456

    float* o_ptr = 0;
    float* s_ptr = 0;
    if ((long long)out_size == OUT_O_N + OUT_S_N) {
        o_ptr = (float*)d_out;
        s_ptr = (float*)d_out + OUT_O_N;
    } else if ((long long)out_size == OUT_O_N) {
        o_ptr = (float*)d_out;
    } else if ((long long)out_size == OUT_S_N) {
        s_ptr = (float*)d_out;
    } else {
        o_ptr = (float*)d_out;   // fallback: at least produce the primary output
    }

    const int smem_bytes = SMEM_FLOATS * (int)sizeof(float);  // 106,496 B
    cudaFuncSetAttribute(attn_mma_kernel,
                         cudaFuncAttributeMaxDynamicSharedMemorySize, smem_bytes);

    dim3 grid(SS / BM, HH, BB);   // (16, 16, 4) = 1024 CTAs
    dim3 block(256);
    attn_mma_kernel<<<grid, block, smem_bytes>>>(q, k, v, mask, o_ptr, s_ptr);
}